// round 3
// baseline (speedup 1.0000x reference)
#include <cuda_runtime.h>
#include <cuda_bf16.h>
#include <math.h>

// Problem constants
#define BB    256
#define SS    196
#define DD    384
#define HH    12
#define DK    32
#define DV    64
#define QKVD  1536          // 12 * (32+32+64)
#define PROJ  768           // 12 * 64
#define MM    (BB*SS)       // 50176 = 392 * 128
#define QSCALE 0.17677669529663687f  // 1/sqrt(32)

// Scratch (device globals: allocation-free rule)
__device__ float g_qkv[(size_t)MM * QKVD];   // 308 MB
__device__ float g_att[(size_t)MM * PROJ];   // 154 MB

// ---------------------------------------------------------------------------
// GEMM C[M,N] = A[M,K] @ W[K,N], fused BN epilogue (+optional q-scale fold)
// BM=BN=128, BK=8, 256 threads, 8x8 microtile. All dims divide exactly.
// ---------------------------------------------------------------------------
__global__ __launch_bounds__(256, 2)
void gemm_bn_kernel(const float* __restrict__ A,
                    const float* __restrict__ W,
                    const float* __restrict__ gamma,
                    const float* __restrict__ beta,
                    const float* __restrict__ mean,
                    const float* __restrict__ var,
                    float* __restrict__ C,
                    int N, int K, int foldq)
{
    __shared__ float As[8][128];
    __shared__ float Bs[8][128];

    const int tid  = threadIdx.x;
    const int arow = tid >> 1;          // 0..127
    const int acol = (tid & 1) << 2;    // 0 or 4
    const int brow = tid >> 5;          // 0..7
    const int bcol = (tid & 31) << 2;   // 0..124
    const int rb   = (tid >> 4) << 3;   // thread row base
    const int cb   = (tid & 15) << 3;   // thread col base

    const float* Aptr = A + (size_t)(blockIdx.y * 128 + arow) * K;
    const float* Bptr = W + (size_t)brow * N + blockIdx.x * 128 + bcol;

    float acc[8][8];
#pragma unroll
    for (int i = 0; i < 8; i++)
#pragma unroll
        for (int j = 0; j < 8; j++) acc[i][j] = 0.f;

    for (int k0 = 0; k0 < K; k0 += 8) {
        float4 av = *(const float4*)(Aptr + k0 + acol);
        float4 bv = *(const float4*)(Bptr + (size_t)k0 * N);
        As[acol + 0][arow] = av.x;
        As[acol + 1][arow] = av.y;
        As[acol + 2][arow] = av.z;
        As[acol + 3][arow] = av.w;
        *(float4*)&Bs[brow][bcol] = bv;
        __syncthreads();
#pragma unroll
        for (int kk = 0; kk < 8; kk++) {
            float a[8], b[8];
#pragma unroll
            for (int i = 0; i < 8; i++) a[i] = As[kk][rb + i];
#pragma unroll
            for (int j = 0; j < 8; j++) b[j] = Bs[kk][cb + j];
#pragma unroll
            for (int i = 0; i < 8; i++)
#pragma unroll
                for (int j = 0; j < 8; j++)
                    acc[i][j] += a[i] * b[j];
        }
        __syncthreads();
    }

    // Fused BN epilogue: y = x*g + bv, g = gamma*rsqrt(var+eps), bv = beta-mean*g
    const int    ccol0 = blockIdx.x * 128 + cb;
    const size_t crow0 = (size_t)blockIdx.y * 128 + rb;
#pragma unroll
    for (int j = 0; j < 8; j++) {
        int   c  = ccol0 + j;
        float g  = gamma[c] * rsqrtf(var[c] + 1e-5f);
        float bv = beta[c] - mean[c] * g;
        if (foldq && ((c & 127) < DK)) { g *= QSCALE; bv *= QSCALE; }
#pragma unroll
        for (int i = 0; i < 8; i++)
            C[(crow0 + i) * N + c] = acc[i][j] * g + bv;
    }
}

// ---------------------------------------------------------------------------
// Attention: one block per (b,h). Full 196x196 scores in SMEM.
// SMEM: attn[196*196] | buf[2*196*33] (q,k; later aliased by v[196*65])
// Phase1: scores = q@k^T (+bias gather), 2i x 4j register tile
// Phase2: softmax (deferred 1/sum), then v load into aliased buffer
// Phase3: out = scores@v, 2i x 4d register tile, fused hard_swish
// ---------------------------------------------------------------------------
__global__ __launch_bounds__(256)
void attn_kernel(const float* __restrict__ qkv,
                 const float* __restrict__ ab,     // [12,196]
                 const int*   __restrict__ bidx,   // [196*196]
                 float* __restrict__ attout)       // [MM, 768]
{
    extern __shared__ float smm[];
    float* attn_s = smm;                  // 196*196
    float* qs     = smm + SS * SS;        // 196*33 (padded)
    float* ks     = qs + SS * 33;         // 196*33
    float* vs     = qs;                   // alias: 196*65 <= 2*196*33
    __shared__ float habias[SS];
    __shared__ float rsum[SS];

    const int tid = threadIdx.x;
    const int b   = blockIdx.x / HH;
    const int h   = blockIdx.x - b * HH;
    const float* base = qkv + (size_t)b * SS * QKVD + h * 128;

    // load q (already scaled), k
    for (int idx = tid; idx < SS * DK; idx += 256) {
        int s = idx >> 5, d = idx & 31;
        const float* p = base + (size_t)s * QKVD + d;
        qs[s * 33 + d] = p[0];
        ks[s * 33 + d] = p[DK];
    }
    for (int idx = tid; idx < SS; idx += 256) habias[idx] = ab[h * SS + idx];
    __syncthreads();

    // Phase 1: scores
    for (int idx = tid; idx < 98 * 49; idx += 256) {
        int i0 = idx / 49;
        int g  = idx - i0 * 49;
        int i1 = i0 + 98;
        float a00 = 0.f, a01 = 0.f, a02 = 0.f, a03 = 0.f;
        float a10 = 0.f, a11 = 0.f, a12 = 0.f, a13 = 0.f;
#pragma unroll 8
        for (int d = 0; d < DK; d++) {
            float q0 = qs[i0 * 33 + d];
            float q1 = qs[i1 * 33 + d];
            float k0 = ks[(g      ) * 33 + d];
            float k1 = ks[(g +  49) * 33 + d];
            float k2 = ks[(g +  98) * 33 + d];
            float k3 = ks[(g + 147) * 33 + d];
            a00 += q0 * k0; a01 += q0 * k1; a02 += q0 * k2; a03 += q0 * k3;
            a10 += q1 * k0; a11 += q1 * k1; a12 += q1 * k2; a13 += q1 * k3;
        }
        float r0[4] = {a00, a01, a02, a03};
        float r1[4] = {a10, a11, a12, a13};
#pragma unroll
        for (int m = 0; m < 4; m++) {
            int j = g + 49 * m;
            attn_s[i0 * SS + j] = r0[m] + habias[bidx[i0 * SS + j]];
            attn_s[i1 * SS + j] = r1[m] + habias[bidx[i1 * SS + j]];
        }
    }
    __syncthreads();

    // Phase 2: softmax rows (store exp, keep reciprocal sum)
    if (tid < SS) {
        float* row = attn_s + tid * SS;
        float mx = -1e30f;
        for (int j = 0; j < SS; j++) mx = fmaxf(mx, row[j]);
        float sum = 0.f;
        for (int j = 0; j < SS; j++) {
            float e = __expf(row[j] - mx);
            row[j] = e;
            sum += e;
        }
        rsum[tid] = 1.f / sum;
    }
    // v load into aliased q/k region (q/k reads all completed before prior barrier)
    for (int idx = tid; idx < SS * DV; idx += 256) {
        int s = idx >> 6, d = idx & 63;
        vs[s * 65 + d] = base[(size_t)s * QKVD + 2 * DK + d];
    }
    __syncthreads();

    // Phase 3: out = scores @ v, fused hard_swish
    float* outb = attout + (size_t)b * SS * PROJ + h * DV;
    for (int idx = tid; idx < 98 * 16; idx += 256) {
        int i0 = idx >> 4;
        int d0 = idx & 15;
        int i1 = i0 + 98;
        const float* r0 = attn_s + i0 * SS;
        const float* r1 = attn_s + i1 * SS;
        float a00 = 0.f, a01 = 0.f, a02 = 0.f, a03 = 0.f;
        float a10 = 0.f, a11 = 0.f, a12 = 0.f, a13 = 0.f;
#pragma unroll 4
        for (int j = 0; j < SS; j++) {
            float s0 = r0[j];
            float s1 = r1[j];
            const float* vr = vs + j * 65 + d0;
            float v0 = vr[0], v1 = vr[16], v2 = vr[32], v3 = vr[48];
            a00 += s0 * v0; a01 += s0 * v1; a02 += s0 * v2; a03 += s0 * v3;
            a10 += s1 * v0; a11 += s1 * v1; a12 += s1 * v2; a13 += s1 * v3;
        }
        float inv0 = rsum[i0], inv1 = rsum[i1];
        float o0[4] = {a00 * inv0, a01 * inv0, a02 * inv0, a03 * inv0};
        float o1[4] = {a10 * inv1, a11 * inv1, a12 * inv1, a13 * inv1};
#pragma unroll
        for (int m = 0; m < 4; m++) {
            int d = d0 + 16 * m;
            float x0 = o0[m], x1 = o1[m];
            x0 = x0 * (fminf(fmaxf(x0 + 3.f, 0.f), 6.f) * (1.f / 6.f));
            x1 = x1 * (fminf(fmaxf(x1 + 3.f, 0.f), 6.f) * (1.f / 6.f));
            outb[(size_t)i0 * PROJ + d] = x0;
            outb[(size_t)i1 * PROJ + d] = x1;
        }
    }
}

// ---------------------------------------------------------------------------
extern "C" void kernel_launch(void* const* d_in, const int* in_sizes, int n_in,
                              void* d_out, int out_size)
{
    const float* hidden = (const float*)d_in[0];
    const float* Wqkv   = (const float*)d_in[1];
    const float* g1     = (const float*)d_in[2];
    const float* b1     = (const float*)d_in[3];
    const float* m1     = (const float*)d_in[4];
    const float* v1     = (const float*)d_in[5];
    const float* Wproj  = (const float*)d_in[6];
    const float* g2     = (const float*)d_in[7];
    const float* b2     = (const float*)d_in[8];
    const float* m2     = (const float*)d_in[9];
    const float* v2     = (const float*)d_in[10];
    const float* ab     = (const float*)d_in[11];
    const int*   bidx   = (const int*)  d_in[12];
    float* out = (float*)d_out;

    float *qkv_buf, *att_buf;
    cudaGetSymbolAddress((void**)&qkv_buf, g_qkv);
    cudaGetSymbolAddress((void**)&att_buf, g_att);

    const int attn_smem = (SS * SS + 2 * SS * 33) * (int)sizeof(float); // 205408 B
    cudaFuncSetAttribute(attn_kernel,
                         cudaFuncAttributeMaxDynamicSharedMemorySize, attn_smem);

    // 1) QKV GEMM + BN1 (+q scale fold)
    gemm_bn_kernel<<<dim3(QKVD / 128, MM / 128), 256>>>(
        hidden, Wqkv, g1, b1, m1, v1, qkv_buf, QKVD, DD, 1);

    // 2) attention + hard_swish
    attn_kernel<<<BB * HH, 256, attn_smem>>>(qkv_buf, ab, bidx, att_buf);

    // 3) proj GEMM + BN2
    gemm_bn_kernel<<<dim3(DD / 128, MM / 128), 256>>>(
        att_buf, Wproj, g2, b2, m2, v2, out, DD, PROJ, 0);
}

// round 4
// speedup vs baseline: 1.0013x; 1.0013x over previous
#include <cuda_runtime.h>
#include <cuda_bf16.h>
#include <math.h>

// Problem constants
#define BB    256
#define SS    196
#define DD    384
#define HH    12
#define DK    32
#define DV    64
#define QKVD  1536          // 12 * (32+32+64)
#define PROJ  768           // 12 * 64
#define MM    (BB*SS)       // 50176 = 392 * 128
#define QSCALE 0.17677669529663687f  // 1/sqrt(32)

// Scratch (device globals: allocation-free rule)
__device__ float g_qkv[(size_t)MM * QKVD];   // 308 MB
__device__ float g_att[(size_t)MM * PROJ];   // 154 MB

// ---------------------------------------------------------------------------
// GEMM C[M,N] = A[M,K] @ W[K,N], fused BN epilogue (+optional q-scale fold)
// BM=BN=128, BK=8, 256 threads, 8x8 microtile. All dims divide exactly.
// ---------------------------------------------------------------------------
__global__ __launch_bounds__(256, 2)
void gemm_bn_kernel(const float* __restrict__ A,
                    const float* __restrict__ W,
                    const float* __restrict__ gamma,
                    const float* __restrict__ beta,
                    const float* __restrict__ mean,
                    const float* __restrict__ var,
                    float* __restrict__ C,
                    int N, int K, int foldq)
{
    __shared__ float As[8][128];
    __shared__ float Bs[8][128];

    const int tid  = threadIdx.x;
    const int arow = tid >> 1;          // 0..127
    const int acol = (tid & 1) << 2;    // 0 or 4
    const int brow = tid >> 5;          // 0..7
    const int bcol = (tid & 31) << 2;   // 0..124
    const int rb   = (tid >> 4) << 3;   // thread row base
    const int cb   = (tid & 15) << 3;   // thread col base

    const float* Aptr = A + (size_t)(blockIdx.y * 128 + arow) * K;
    const float* Bptr = W + (size_t)brow * N + blockIdx.x * 128 + bcol;

    float acc[8][8];
#pragma unroll
    for (int i = 0; i < 8; i++)
#pragma unroll
        for (int j = 0; j < 8; j++) acc[i][j] = 0.f;

    for (int k0 = 0; k0 < K; k0 += 8) {
        float4 av = *(const float4*)(Aptr + k0 + acol);
        float4 bv = *(const float4*)(Bptr + (size_t)k0 * N);
        As[acol + 0][arow] = av.x;
        As[acol + 1][arow] = av.y;
        As[acol + 2][arow] = av.z;
        As[acol + 3][arow] = av.w;
        *(float4*)&Bs[brow][bcol] = bv;
        __syncthreads();
#pragma unroll
        for (int kk = 0; kk < 8; kk++) {
            float a[8], b[8];
#pragma unroll
            for (int i = 0; i < 8; i++) a[i] = As[kk][rb + i];
#pragma unroll
            for (int j = 0; j < 8; j++) b[j] = Bs[kk][cb + j];
#pragma unroll
            for (int i = 0; i < 8; i++)
#pragma unroll
                for (int j = 0; j < 8; j++)
                    acc[i][j] += a[i] * b[j];
        }
        __syncthreads();
    }

    // Fused BN epilogue: y = x*g + bv, g = gamma*rsqrt(var+eps), bv = beta-mean*g
    const int    ccol0 = blockIdx.x * 128 + cb;
    const size_t crow0 = (size_t)blockIdx.y * 128 + rb;
#pragma unroll
    for (int j = 0; j < 8; j++) {
        int   c  = ccol0 + j;
        float g  = gamma[c] * rsqrtf(var[c] + 1e-5f);
        float bv = beta[c] - mean[c] * g;
        if (foldq && ((c & 127) < DK)) { g *= QSCALE; bv *= QSCALE; }
#pragma unroll
        for (int i = 0; i < 8; i++)
            C[(crow0 + i) * N + c] = acc[i][j] * g + bv;
    }
}

// ---------------------------------------------------------------------------
// Attention: one block per (b,h). Full 196x196 scores in SMEM.
// SMEM: attn[196*196] | buf[2*196*33] (q,k; later aliased by v[196*65])
// Phase1: scores = q@k^T (+bias gather), 2i x 4j register tile
// Phase2: softmax (deferred 1/sum), then v load into aliased buffer
// Phase3: out = scores@v, 2i x 4d register tile, fused hard_swish
// ---------------------------------------------------------------------------
__global__ __launch_bounds__(256)
void attn_kernel(const float* __restrict__ qkv,
                 const float* __restrict__ ab,     // [12,196]
                 const int*   __restrict__ bidx,   // [196*196]
                 float* __restrict__ attout)       // [MM, 768]
{
    extern __shared__ float smm[];
    float* attn_s = smm;                  // 196*196
    float* qs     = smm + SS * SS;        // 196*33 (padded)
    float* ks     = qs + SS * 33;         // 196*33
    float* vs     = qs;                   // alias: 196*65 <= 2*196*33
    __shared__ float habias[SS];
    __shared__ float rsum[SS];

    const int tid = threadIdx.x;
    const int b   = blockIdx.x / HH;
    const int h   = blockIdx.x - b * HH;
    const float* base = qkv + (size_t)b * SS * QKVD + h * 128;

    // load q (already scaled), k
    for (int idx = tid; idx < SS * DK; idx += 256) {
        int s = idx >> 5, d = idx & 31;
        const float* p = base + (size_t)s * QKVD + d;
        qs[s * 33 + d] = p[0];
        ks[s * 33 + d] = p[DK];
    }
    for (int idx = tid; idx < SS; idx += 256) habias[idx] = ab[h * SS + idx];
    __syncthreads();

    // Phase 1: scores
    for (int idx = tid; idx < 98 * 49; idx += 256) {
        int i0 = idx / 49;
        int g  = idx - i0 * 49;
        int i1 = i0 + 98;
        float a00 = 0.f, a01 = 0.f, a02 = 0.f, a03 = 0.f;
        float a10 = 0.f, a11 = 0.f, a12 = 0.f, a13 = 0.f;
#pragma unroll 8
        for (int d = 0; d < DK; d++) {
            float q0 = qs[i0 * 33 + d];
            float q1 = qs[i1 * 33 + d];
            float k0 = ks[(g      ) * 33 + d];
            float k1 = ks[(g +  49) * 33 + d];
            float k2 = ks[(g +  98) * 33 + d];
            float k3 = ks[(g + 147) * 33 + d];
            a00 += q0 * k0; a01 += q0 * k1; a02 += q0 * k2; a03 += q0 * k3;
            a10 += q1 * k0; a11 += q1 * k1; a12 += q1 * k2; a13 += q1 * k3;
        }
        float r0[4] = {a00, a01, a02, a03};
        float r1[4] = {a10, a11, a12, a13};
#pragma unroll
        for (int m = 0; m < 4; m++) {
            int j = g + 49 * m;
            attn_s[i0 * SS + j] = r0[m] + habias[bidx[i0 * SS + j]];
            attn_s[i1 * SS + j] = r1[m] + habias[bidx[i1 * SS + j]];
        }
    }
    __syncthreads();

    // Phase 2: softmax rows (store exp, keep reciprocal sum)
    if (tid < SS) {
        float* row = attn_s + tid * SS;
        float mx = -1e30f;
        for (int j = 0; j < SS; j++) mx = fmaxf(mx, row[j]);
        float sum = 0.f;
        for (int j = 0; j < SS; j++) {
            float e = __expf(row[j] - mx);
            row[j] = e;
            sum += e;
        }
        rsum[tid] = 1.f / sum;
    }
    // v load into aliased q/k region (q/k reads all completed before prior barrier)
    for (int idx = tid; idx < SS * DV; idx += 256) {
        int s = idx >> 6, d = idx & 63;
        vs[s * 65 + d] = base[(size_t)s * QKVD + 2 * DK + d];
    }
    __syncthreads();

    // Phase 3: out = scores @ v, fused hard_swish
    float* outb = attout + (size_t)b * SS * PROJ + h * DV;
    for (int idx = tid; idx < 98 * 16; idx += 256) {
        int i0 = idx >> 4;
        int d0 = idx & 15;
        int i1 = i0 + 98;
        const float* r0 = attn_s + i0 * SS;
        const float* r1 = attn_s + i1 * SS;
        float a00 = 0.f, a01 = 0.f, a02 = 0.f, a03 = 0.f;
        float a10 = 0.f, a11 = 0.f, a12 = 0.f, a13 = 0.f;
#pragma unroll 4
        for (int j = 0; j < SS; j++) {
            float s0 = r0[j];
            float s1 = r1[j];
            const float* vr = vs + j * 65 + d0;
            float v0 = vr[0], v1 = vr[16], v2 = vr[32], v3 = vr[48];
            a00 += s0 * v0; a01 += s0 * v1; a02 += s0 * v2; a03 += s0 * v3;
            a10 += s1 * v0; a11 += s1 * v1; a12 += s1 * v2; a13 += s1 * v3;
        }
        float inv0 = rsum[i0], inv1 = rsum[i1];
        float o0[4] = {a00 * inv0, a01 * inv0, a02 * inv0, a03 * inv0};
        float o1[4] = {a10 * inv1, a11 * inv1, a12 * inv1, a13 * inv1};
#pragma unroll
        for (int m = 0; m < 4; m++) {
            int d = d0 + 16 * m;
            float x0 = o0[m], x1 = o1[m];
            x0 = x0 * (fminf(fmaxf(x0 + 3.f, 0.f), 6.f) * (1.f / 6.f));
            x1 = x1 * (fminf(fmaxf(x1 + 3.f, 0.f), 6.f) * (1.f / 6.f));
            outb[(size_t)i0 * PROJ + d] = x0;
            outb[(size_t)i1 * PROJ + d] = x1;
        }
    }
}

// ---------------------------------------------------------------------------
extern "C" void kernel_launch(void* const* d_in, const int* in_sizes, int n_in,
                              void* d_out, int out_size)
{
    const float* hidden = (const float*)d_in[0];
    const float* Wqkv   = (const float*)d_in[1];
    const float* g1     = (const float*)d_in[2];
    const float* b1     = (const float*)d_in[3];
    const float* m1     = (const float*)d_in[4];
    const float* v1     = (const float*)d_in[5];
    const float* Wproj  = (const float*)d_in[6];
    const float* g2     = (const float*)d_in[7];
    const float* b2     = (const float*)d_in[8];
    const float* m2     = (const float*)d_in[9];
    const float* v2     = (const float*)d_in[10];
    const float* ab     = (const float*)d_in[11];
    const int*   bidx   = (const int*)  d_in[12];
    float* out = (float*)d_out;

    float *qkv_buf, *att_buf;
    cudaGetSymbolAddress((void**)&qkv_buf, g_qkv);
    cudaGetSymbolAddress((void**)&att_buf, g_att);

    const int attn_smem = (SS * SS + 2 * SS * 33) * (int)sizeof(float); // 205408 B
    cudaFuncSetAttribute(attn_kernel,
                         cudaFuncAttributeMaxDynamicSharedMemorySize, attn_smem);

    // 1) QKV GEMM + BN1 (+q scale fold)
    gemm_bn_kernel<<<dim3(QKVD / 128, MM / 128), 256>>>(
        hidden, Wqkv, g1, b1, m1, v1, qkv_buf, QKVD, DD, 1);

    // 2) attention + hard_swish
    attn_kernel<<<BB * HH, 256, attn_smem>>>(qkv_buf, ab, bidx, att_buf);

    // 3) proj GEMM + BN2
    gemm_bn_kernel<<<dim3(DD / 128, MM / 128), 256>>>(
        att_buf, Wproj, g2, b2, m2, v2, out, DD, PROJ, 0);
}

// round 7
// speedup vs baseline: 1.8481x; 1.8457x over previous
#include <cuda_runtime.h>
#include <cuda_bf16.h>
#include <math.h>
#include <cstdint>

// Problem constants
#define BB    256
#define SS    196
#define DD    384
#define HH    12
#define DK    32
#define DV    64
#define QKVD  1536          // 12 * (32+32+64)
#define PROJ  768           // 12 * 64
#define MM    (BB*SS)       // 50176 = 392 * 128
#define QSCALE 0.17677669529663687f  // 1/sqrt(32)
#define ATHR  512

// Scratch (device globals: allocation-free rule)
__device__ float g_qkv[(size_t)MM * QKVD];   // 308 MB
__device__ float g_att[(size_t)MM * PROJ];   // 154 MB
__device__ float g_wt1[(size_t)QKVD * DD];   // W_qkv^T, scale-folded, tf32
__device__ float g_wt2[(size_t)DD * PROJ];   // W_proj^T, scale-folded, tf32
__device__ float g_b1v[QKVD];
__device__ float g_b2v[DD];

__device__ __forceinline__ uint32_t f2tf32(float x) {
    uint32_t u;
    asm("cvt.rna.tf32.f32 %0, %1;" : "=r"(u) : "f"(x));
    return u;
}

// m16n8k8 tf32 mma (sm_80+; works on plain sm_100 target)
__device__ __forceinline__ void mma1688(float* c, const uint32_t* a, const uint32_t* b) {
    asm volatile(
        "mma.sync.aligned.m16n8k8.row.col.f32.tf32.tf32.f32 "
        "{%0,%1,%2,%3}, {%4,%5,%6,%7}, {%8,%9}, {%0,%1,%2,%3};"
        : "+f"(c[0]), "+f"(c[1]), "+f"(c[2]), "+f"(c[3])
        : "r"(a[0]), "r"(a[1]), "r"(a[2]), "r"(a[3]),
          "r"(b[0]), "r"(b[1]));
}

// ---------------------------------------------------------------------------
// Weight prep: WT[n,k] = tf32(W[k,n] * s[n]), bias[n] = beta - mean*s (+folds)
// ---------------------------------------------------------------------------
__global__ void prep_w_kernel(const float* __restrict__ W,
                              const float* __restrict__ gamma,
                              const float* __restrict__ beta,
                              const float* __restrict__ mean,
                              const float* __restrict__ var,
                              float* __restrict__ WT,
                              float* __restrict__ bias,
                              int K, int N, int foldq)
{
    int n = blockIdx.x;
    float s  = gamma[n] * rsqrtf(var[n] + 1e-5f);
    float bv = beta[n] - mean[n] * s;
    if (foldq && ((n & 127) < DK)) { s *= QSCALE; bv *= QSCALE; }
    if (threadIdx.x == 0) bias[n] = bv;
    for (int k = threadIdx.x; k < K; k += blockDim.x) {
        float w = W[(size_t)k * N + n] * s;
        WT[(size_t)n * K + k] = __uint_as_float(f2tf32(w));
    }
}

// ---------------------------------------------------------------------------
// mma.sync tf32 GEMM: C[M,N] = A[M,K] @ WT[N,K]^T + bias[N]
// CTA 128x128, BK=32, 256 thr (8 warps 2x4), warp tile 64x32 (4x4 m16n8k8).
// SMEM: A[2][128][36], B[2][128][36] (pad 36 -> conflict-free frag loads).
// Register-staged double buffer: LDG(next) | compute(cur) | STS(next) | bar.
// ---------------------------------------------------------------------------
#define APAD 36
#define ABUF (128 * APAD)          // floats per buffer

template<int NKT>
__global__ void __launch_bounds__(256)
gemm_mma(const float* __restrict__ A, const float* __restrict__ WT,
         const float* __restrict__ bias, float* __restrict__ C, int N)
{
    constexpr int K = NKT * 32;
    extern __shared__ float sm[];
    float* sA = sm;                 // [2][ABUF]
    float* sB = sm + 2 * ABUF;      // [2][ABUF]

    const int tid    = threadIdx.x;
    const int wid    = tid >> 5;
    const int lane   = tid & 31;
    const int warp_m = wid >> 2;    // 0..1
    const int warp_n = wid & 3;     // 0..3
    const int g      = lane >> 2;   // 0..7
    const int t      = lane & 3;    // 0..3

    const float* Ab = A  + (size_t)(blockIdx.y * 128) * K;
    const float* Bb = WT + (size_t)(blockIdx.x * 128) * K;

    // per-thread quad coords (4 quads each for A and B): u = i*256+tid
    // row = u>>3 (0..127), q = u&7 (k-quad)
    float acc[4][4][4];
#pragma unroll
    for (int mi = 0; mi < 4; mi++)
#pragma unroll
        for (int nj = 0; nj < 4; nj++)
#pragma unroll
            for (int r = 0; r < 4; r++) acc[mi][nj][r] = 0.f;

    float4 ar[4], br[4];

    // prologue: load + store k-tile 0
#pragma unroll
    for (int i = 0; i < 4; i++) {
        int u = i * 256 + tid, row = u >> 3, q = u & 7;
        ar[i] = *(const float4*)(Ab + (size_t)row * K + q * 4);
        br[i] = *(const float4*)(Bb + (size_t)row * K + q * 4);
    }
#pragma unroll
    for (int i = 0; i < 4; i++) {
        int u = i * 256 + tid, row = u >> 3, q = u & 7;
        uint4 ua;
        ua.x = f2tf32(ar[i].x); ua.y = f2tf32(ar[i].y);
        ua.z = f2tf32(ar[i].z); ua.w = f2tf32(ar[i].w);
        *(uint4*)(sA + row * APAD + q * 4) = ua;
        *(float4*)(sB + row * APAD + q * 4) = br[i];
    }
    __syncthreads();

    for (int kt = 0; kt < NKT; kt++) {
        const int buf = kt & 1;
        const float* cA = sA + buf * ABUF;
        const float* cB = sB + buf * ABUF;

        if (kt + 1 < NKT) {
            const int k0 = (kt + 1) * 32;
#pragma unroll
            for (int i = 0; i < 4; i++) {
                int u = i * 256 + tid, row = u >> 3, q = u & 7;
                ar[i] = *(const float4*)(Ab + (size_t)row * K + k0 + q * 4);
                br[i] = *(const float4*)(Bb + (size_t)row * K + k0 + q * 4);
            }
        }

        // compute current tile: 4 k8 steps
#pragma unroll
        for (int ki = 0; ki < 4; ki++) {
            uint32_t af[4][4], bf[4][2];
#pragma unroll
            for (int mi = 0; mi < 4; mi++) {
                const float* p = cA + (warp_m * 64 + mi * 16 + g) * APAD + ki * 8 + t;
                af[mi][0] = __float_as_uint(p[0]);
                af[mi][1] = __float_as_uint(p[8 * APAD]);
                af[mi][2] = __float_as_uint(p[4]);
                af[mi][3] = __float_as_uint(p[8 * APAD + 4]);
            }
#pragma unroll
            for (int nj = 0; nj < 4; nj++) {
                const float* p = cB + (warp_n * 32 + nj * 8 + g) * APAD + ki * 8 + t;
                bf[nj][0] = __float_as_uint(p[0]);
                bf[nj][1] = __float_as_uint(p[4]);
            }
#pragma unroll
            for (int mi = 0; mi < 4; mi++)
#pragma unroll
                for (int nj = 0; nj < 4; nj++)
                    mma1688(acc[mi][nj], af[mi], bf[nj]);
        }

        if (kt + 1 < NKT) {
            float* nA = sA + ((kt + 1) & 1) * ABUF;
            float* nB = sB + ((kt + 1) & 1) * ABUF;
#pragma unroll
            for (int i = 0; i < 4; i++) {
                int u = i * 256 + tid, row = u >> 3, q = u & 7;
                uint4 ua;
                ua.x = f2tf32(ar[i].x); ua.y = f2tf32(ar[i].y);
                ua.z = f2tf32(ar[i].z); ua.w = f2tf32(ar[i].w);
                *(uint4*)(nA + row * APAD + q * 4) = ua;
                *(float4*)(nB + row * APAD + q * 4) = br[i];
            }
        }
        __syncthreads();
    }

    // Epilogue: add bias, store (float2 per fragment row)
    const int row0 = blockIdx.y * 128 + warp_m * 64 + g;
    const int col0 = blockIdx.x * 128 + warp_n * 32 + t * 2;
#pragma unroll
    for (int nj = 0; nj < 4; nj++) {
        const int c = col0 + nj * 8;
        const float2 bb = *(const float2*)(bias + c);
#pragma unroll
        for (int mi = 0; mi < 4; mi++) {
            const int r = row0 + mi * 16;
            float2 o0, o1;
            o0.x = acc[mi][nj][0] + bb.x; o0.y = acc[mi][nj][1] + bb.y;
            o1.x = acc[mi][nj][2] + bb.x; o1.y = acc[mi][nj][3] + bb.y;
            *(float2*)(C + (size_t)r * N + c)       = o0;
            *(float2*)(C + (size_t)(r + 8) * N + c) = o1;
        }
    }
}

// ---------------------------------------------------------------------------
// Attention: one block per (b,h). Full 196x196 scores in SMEM.
// 512 threads; warp-per-row softmax with shfl reductions.
// ---------------------------------------------------------------------------
__global__ __launch_bounds__(ATHR)
void attn_kernel(const float* __restrict__ qkv,
                 const float* __restrict__ ab,     // [12,196]
                 const int*   __restrict__ bidx,   // [196*196]
                 float* __restrict__ attout)       // [MM, 768]
{
    extern __shared__ float smm[];
    float* attn_s = smm;                  // 196*196
    float* qs     = smm + SS * SS;        // 196*33 (padded)
    float* ks     = qs + SS * 33;         // 196*33
    float* vs     = qs;                   // alias: 196*65 <= 2*196*33
    __shared__ float habias[SS];
    __shared__ float rsum[SS];

    const int tid  = threadIdx.x;
    const int wid  = tid >> 5;
    const int lane = tid & 31;
    const int b    = blockIdx.x / HH;
    const int h    = blockIdx.x - b * HH;
    const float* base = qkv + (size_t)b * SS * QKVD + h * 128;

    for (int idx = tid; idx < SS * DK; idx += ATHR) {
        int s = idx >> 5, d = idx & 31;
        const float* p = base + (size_t)s * QKVD + d;
        qs[s * 33 + d] = p[0];
        ks[s * 33 + d] = p[DK];
    }
    for (int idx = tid; idx < SS; idx += ATHR) habias[idx] = ab[h * SS + idx];
    __syncthreads();

    // Phase 1: scores
    for (int idx = tid; idx < 98 * 49; idx += ATHR) {
        int i0 = idx / 49;
        int gg = idx - i0 * 49;
        int i1 = i0 + 98;
        float a00 = 0.f, a01 = 0.f, a02 = 0.f, a03 = 0.f;
        float a10 = 0.f, a11 = 0.f, a12 = 0.f, a13 = 0.f;
#pragma unroll 8
        for (int d = 0; d < DK; d++) {
            float q0 = qs[i0 * 33 + d];
            float q1 = qs[i1 * 33 + d];
            float k0 = ks[(gg      ) * 33 + d];
            float k1 = ks[(gg +  49) * 33 + d];
            float k2 = ks[(gg +  98) * 33 + d];
            float k3 = ks[(gg + 147) * 33 + d];
            a00 += q0 * k0; a01 += q0 * k1; a02 += q0 * k2; a03 += q0 * k3;
            a10 += q1 * k0; a11 += q1 * k1; a12 += q1 * k2; a13 += q1 * k3;
        }
        float r0[4] = {a00, a01, a02, a03};
        float r1[4] = {a10, a11, a12, a13};
#pragma unroll
        for (int m = 0; m < 4; m++) {
            int j = gg + 49 * m;
            attn_s[i0 * SS + j] = r0[m] + habias[bidx[i0 * SS + j]];
            attn_s[i1 * SS + j] = r1[m] + habias[bidx[i1 * SS + j]];
        }
    }
    __syncthreads();

    // Phase 2a: warp-per-row softmax (store exp, keep reciprocal sum)
    for (int r = wid; r < SS; r += ATHR / 32) {
        float* row = attn_s + r * SS;
        float mx = -1e30f;
        for (int j = lane; j < SS; j += 32) mx = fmaxf(mx, row[j]);
#pragma unroll
        for (int o = 16; o > 0; o >>= 1)
            mx = fmaxf(mx, __shfl_xor_sync(0xffffffffu, mx, o));
        float sum = 0.f;
        for (int j = lane; j < SS; j += 32) {
            float e = __expf(row[j] - mx);
            row[j] = e;
            sum += e;
        }
#pragma unroll
        for (int o = 16; o > 0; o >>= 1)
            sum += __shfl_xor_sync(0xffffffffu, sum, o);
        if (lane == 0) rsum[r] = 1.f / sum;
    }
    // Phase 2b: v load into aliased q/k region (q/k dead after phase 1 barrier)
    for (int idx = tid; idx < SS * DV; idx += ATHR) {
        int s = idx >> 6, d = idx & 63;
        vs[s * 65 + d] = base[(size_t)s * QKVD + 2 * DK + d];
    }
    __syncthreads();

    // Phase 3: out = scores @ v, fused hard_swish
    float* outb = attout + (size_t)b * SS * PROJ + h * DV;
    for (int idx = tid; idx < 98 * 16; idx += ATHR) {
        int i0 = idx >> 4;
        int d0 = idx & 15;
        int i1 = i0 + 98;
        const float* r0 = attn_s + i0 * SS;
        const float* r1 = attn_s + i1 * SS;
        float a00 = 0.f, a01 = 0.f, a02 = 0.f, a03 = 0.f;
        float a10 = 0.f, a11 = 0.f, a12 = 0.f, a13 = 0.f;
#pragma unroll 4
        for (int j = 0; j < SS; j++) {
            float s0 = r0[j];
            float s1 = r1[j];
            const float* vr = vs + j * 65 + d0;
            float v0 = vr[0], v1 = vr[16], v2 = vr[32], v3 = vr[48];
            a00 += s0 * v0; a01 += s0 * v1; a02 += s0 * v2; a03 += s0 * v3;
            a10 += s1 * v0; a11 += s1 * v1; a12 += s1 * v2; a13 += s1 * v3;
        }
        float inv0 = rsum[i0], inv1 = rsum[i1];
        float o0[4] = {a00 * inv0, a01 * inv0, a02 * inv0, a03 * inv0};
        float o1[4] = {a10 * inv1, a11 * inv1, a12 * inv1, a13 * inv1};
#pragma unroll
        for (int m = 0; m < 4; m++) {
            int d = d0 + 16 * m;
            float x0 = o0[m], x1 = o1[m];
            x0 = x0 * (fminf(fmaxf(x0 + 3.f, 0.f), 6.f) * (1.f / 6.f));
            x1 = x1 * (fminf(fmaxf(x1 + 3.f, 0.f), 6.f) * (1.f / 6.f));
            outb[(size_t)i0 * PROJ + d] = x0;
            outb[(size_t)i1 * PROJ + d] = x1;
        }
    }
}

// ---------------------------------------------------------------------------
extern "C" void kernel_launch(void* const* d_in, const int* in_sizes, int n_in,
                              void* d_out, int out_size)
{
    const float* hidden = (const float*)d_in[0];
    const float* Wqkv   = (const float*)d_in[1];
    const float* g1     = (const float*)d_in[2];
    const float* b1     = (const float*)d_in[3];
    const float* m1     = (const float*)d_in[4];
    const float* v1     = (const float*)d_in[5];
    const float* Wproj  = (const float*)d_in[6];
    const float* g2     = (const float*)d_in[7];
    const float* b2     = (const float*)d_in[8];
    const float* m2     = (const float*)d_in[9];
    const float* v2     = (const float*)d_in[10];
    const float* ab     = (const float*)d_in[11];
    const int*   bidx   = (const int*)  d_in[12];
    float* out = (float*)d_out;

    float *qkv_buf, *att_buf, *wt1, *wt2, *b1v, *b2v;
    cudaGetSymbolAddress((void**)&qkv_buf, g_qkv);
    cudaGetSymbolAddress((void**)&att_buf, g_att);
    cudaGetSymbolAddress((void**)&wt1, g_wt1);
    cudaGetSymbolAddress((void**)&wt2, g_wt2);
    cudaGetSymbolAddress((void**)&b1v, g_b1v);
    cudaGetSymbolAddress((void**)&b2v, g_b2v);

    const int gemm_smem = 4 * ABUF * (int)sizeof(float);  // 73728 B
    cudaFuncSetAttribute(gemm_mma<12>,
                         cudaFuncAttributeMaxDynamicSharedMemorySize, gemm_smem);
    cudaFuncSetAttribute(gemm_mma<24>,
                         cudaFuncAttributeMaxDynamicSharedMemorySize, gemm_smem);
    const int attn_smem = (SS * SS + 2 * SS * 33) * (int)sizeof(float); // 205408 B
    cudaFuncSetAttribute(attn_kernel,
                         cudaFuncAttributeMaxDynamicSharedMemorySize, attn_smem);

    // 0) weight prep: transpose + BN-scale fold + tf32 convert
    prep_w_kernel<<<QKVD, 128>>>(Wqkv,  g1, b1, m1, v1, wt1, b1v, DD,  QKVD, 1);
    prep_w_kernel<<<DD,   128>>>(Wproj, g2, b2, m2, v2, wt2, b2v, PROJ, DD,  0);

    // 1) QKV GEMM (mma.sync tf32): M=50176, N=1536, K=384
    gemm_mma<12><<<dim3(QKVD / 128, MM / 128), 256, gemm_smem>>>(
        hidden, wt1, b1v, qkv_buf, QKVD);

    // 2) attention + hard_swish
    attn_kernel<<<BB * HH, ATHR, attn_smem>>>(qkv_buf, ab, bidx, att_buf);

    // 3) proj GEMM (mma.sync tf32): M=50176, N=384, K=768
    gemm_mma<24><<<dim3(DD / 128, MM / 128), 256, gemm_smem>>>(
        att_buf, wt2, b2v, out, DD);
}